// round 17
// baseline (speedup 1.0000x reference)
#include <cuda_runtime.h>
#include <math_constants.h>

#define BB 4
#define LL 2048
#define DD 256
#define HH 8
#define DH 32
#define BHH 32          // B*H
#define UU 40           // FACTOR * ceil(log1p(L)) = 5*8
#define NSPLIT 8        // attention key splits
#define SCH 8           // ssum chunks

// ---------------- device scratch (no allocations allowed) ----------------
__device__ float g_qp[BB * LL * DD];   // projected q, viewed as qf[BH][L][DH]
__device__ float g_kp[BB * LL * DD];   // projected k (B,L,D) layout
__device__ float g_vp[BB * LL * DD];   // projected v (B,L,D) layout
__device__ float g_M[BHH * LL];
__device__ int   g_uniq[LL];
__device__ int   g_cnt[LL];
__device__ int   g_nuniq;
__device__ float g_ssum_p[SCH * BHH * DH];  // per-(chunk,bh) partial weighted key sums
__device__ int   g_top[BHH * UU];
__device__ float g_pm[BHH * NSPLIT * UU];
__device__ float g_pl[BHH * NSPLIT * UU];
__device__ float g_pacc[BHH * NSPLIT * UU * DH];
__device__ float g_attn[BHH * UU * DH];

// ---------------- packed f32x2 helpers (sm_103a FFMA2 path) ----------------
__device__ __forceinline__ unsigned long long pk2(float lo, float hi) {
    unsigned long long r;
    asm("mov.b64 %0, {%1,%2};" : "=l"(r) : "f"(lo), "f"(hi));
    return r;
}
__device__ __forceinline__ void upk2(unsigned long long p, float& lo, float& hi) {
    asm("mov.b64 {%0,%1}, %2;" : "=f"(lo), "=f"(hi) : "l"(p));
}
__device__ __forceinline__ unsigned long long ffma2(unsigned long long a,
                                                    unsigned long long b,
                                                    unsigned long long c) {
    unsigned long long d;
    asm("fma.rn.f32x2 %0, %1, %2, %3;" : "=l"(d) : "l"(a), "l"(b), "l"(c));
    return d;
}

// ---------------- init: zero counts ----------------
__global__ void k_init() {
    int i = blockIdx.x * blockDim.x + threadIdx.x;
    if (i < LL) g_cnt[i] = 0;
    if (i == 0) g_nuniq = 0;
}

// ---------------- unique sampled keys + multiplicities ----------------
__global__ void k_uniq(const int* __restrict__ idxs) {
    int i = blockIdx.x * blockDim.x + threadIdx.x;
    if (i >= LL) return;
    int idx = idxs[i];
    if (atomicAdd(&g_cnt[idx], 1) == 0) {
        int p = atomicAdd(&g_nuniq, 1);
        g_uniq[p] = idx;   // order nondeterministic; consumed only by exact max -> OK
    }
}

// ---------------- fused QKV projection: O = X @ W^T + b ----------------
// X: 8192x256, W: 256x256 row-major. 128x128 tile; thread (ty,tx) owns rows
// ty*8+i, cols 32*jp+tx and 32*jp+16+tx (interleaved -> conflict-free b LDS).
// Inner product via fma.rn.f32x2 (FFMA2): acc chains bitwise-identical to scalar.
__global__ __launch_bounds__(256) void k_proj(
    const float* __restrict__ xq, const float* __restrict__ xk, const float* __restrict__ xv,
    const float* __restrict__ wq, const float* __restrict__ wk, const float* __restrict__ wv,
    const float* __restrict__ bq, const float* __restrict__ bk, const float* __restrict__ bv)
{
    const float* X; const float* W; const float* bias; float* O;
    if (blockIdx.z == 0)      { X = xq; W = wq; bias = bq; O = g_qp; }
    else if (blockIdx.z == 1) { X = xk; W = wk; bias = bk; O = g_kp; }
    else                      { X = xv; W = wv; bias = bv; O = g_vp; }

    __shared__ float Xs[128][33];
    __shared__ float Ws[128][33];
    int tid = threadIdx.x;
    int row0 = blockIdx.y * 128;
    int col0 = blockIdx.x * 128;
    int ty = tid >> 4, tx = tid & 15;

    unsigned long long acc2[8][4];
#pragma unroll
    for (int i = 0; i < 8; i++)
#pragma unroll
        for (int jp = 0; jp < 4; jp++) acc2[i][jp] = 0ull;   // (0.f,0.f)

    for (int k0 = 0; k0 < DD; k0 += 32) {
#pragma unroll
        for (int e = tid; e < 1024; e += 256) {
            int r = e >> 3, c4 = (e & 7) << 2;
            float4 a4 = *(const float4*)(X + (size_t)(row0 + r) * DD + k0 + c4);
            Xs[r][c4] = a4.x; Xs[r][c4 + 1] = a4.y; Xs[r][c4 + 2] = a4.z; Xs[r][c4 + 3] = a4.w;
            float4 w4 = *(const float4*)(W + (size_t)(col0 + r) * DD + k0 + c4);
            Ws[r][c4] = w4.x; Ws[r][c4 + 1] = w4.y; Ws[r][c4 + 2] = w4.z; Ws[r][c4 + 3] = w4.w;
        }
        __syncthreads();
#pragma unroll 8
        for (int kk = 0; kk < 32; kk++) {
            unsigned long long a2[8], b2[4];
#pragma unroll
            for (int i = 0; i < 8; i++) {
                float a = Xs[ty * 8 + i][kk];
                a2[i] = pk2(a, a);
            }
#pragma unroll
            for (int jp = 0; jp < 4; jp++)
                b2[jp] = pk2(Ws[32 * jp + tx][kk], Ws[32 * jp + 16 + tx][kk]);
#pragma unroll
            for (int i = 0; i < 8; i++)
#pragma unroll
                for (int jp = 0; jp < 4; jp++)
                    acc2[i][jp] = ffma2(a2[i], b2[jp], acc2[i][jp]);
        }
        __syncthreads();
    }
#pragma unroll
    for (int i = 0; i < 8; i++) {
        int r = row0 + ty * 8 + i;
#pragma unroll
        for (int jp = 0; jp < 4; jp++) {
            float lo, hi; upk2(acc2[i][jp], lo, hi);
            int clo = col0 + 32 * jp + tx;
            O[(size_t)r * DD + clo]      = lo + bias[clo];
            O[(size_t)r * DD + clo + 16] = hi + bias[clo + 16];
        }
    }
}

// ---------------- per-(bh,chunk) weighted partial sum of sampled keys ----------------
// Unconditional FMA (count 0 contributes 0) + full unroll -> high MLP, no
// load-after-load serialization. grid (32 bh, 8 chunks).
__global__ __launch_bounds__(256) void k_ssum() {
    int bh = blockIdx.x, chunk = blockIdx.y;
    int b = bh >> 3, h = bh & 7;
    __shared__ float cf[256];
    __shared__ float part[8][DH];
    int tid = threadIdx.x;
    int l0 = chunk * (LL / SCH);
    cf[tid] = (float)g_cnt[l0 + tid];
    __syncthreads();
    int d = tid & 31, p = tid >> 5;
    const float* kp = g_kp + ((size_t)(b * LL + l0)) * DD + h * DH + d;
    float s = 0.f;
#pragma unroll
    for (int i = 0; i < 32; i++) {
        int l = p + i * 8;
        s = fmaf(cf[l], kp[(size_t)l * DD], s);
    }
    part[p][d] = s;
    __syncthreads();
    if (tid < DH) {
        float t = 0.f;
#pragma unroll
        for (int p2 = 0; p2 < 8; p2++) t += part[p2][tid];
        g_ssum_p[(chunk * BHH + bh) * DH + tid] = t;
    }
}

// ---------------- M = rowmax(Q @ Ks^T) - (q . ssum)/L over unique sampled keys ----------------
// Same interleaved FFMA2 micro-kernel as k_proj. grid (L/128, BH).
__global__ __launch_bounds__(256) void k_m() {
    int bh = blockIdx.y; int b = bh >> 3, h = bh & 7;
    int q0 = blockIdx.x * 128;
    __shared__ float Qs[128][33];
    __shared__ float Ks[128][33];
    __shared__ float ss[DH];
    int tid = threadIdx.x;
#pragma unroll
    for (int e = tid; e < 1024; e += 256) {
        int r = e >> 3, c4 = (e & 7) << 2;
        float4 v = *(const float4*)(g_qp + ((size_t)(bh * LL + q0 + r)) * DH + c4);
        Qs[r][c4] = v.x; Qs[r][c4 + 1] = v.y; Qs[r][c4 + 2] = v.z; Qs[r][c4 + 3] = v.w;
    }
    if (tid < DH) {
        float t = 0.f;
#pragma unroll
        for (int c = 0; c < SCH; c++) t += g_ssum_p[(c * BHH + bh) * DH + tid];
        ss[tid] = t;
    }
    int nu = g_nuniq;
    int ty = tid >> 4, tx = tid & 15;
    float mrow[8];
#pragma unroll
    for (int i = 0; i < 8; i++) mrow[i] = -CUDART_INF_F;

    for (int base = 0; base < nu; base += 128) {
#pragma unroll
        for (int e = tid; e < 1024; e += 256) {
            int r = e >> 3, c4 = (e & 7) << 2;
            float4 v;
            if (base + r < nu) {
                int row = g_uniq[base + r];
                v = *(const float4*)(g_kp + ((size_t)(b * LL + row)) * DD + h * DH + c4);
            } else { v.x = v.y = v.z = v.w = 0.f; }
            Ks[r][c4] = v.x; Ks[r][c4 + 1] = v.y; Ks[r][c4 + 2] = v.z; Ks[r][c4 + 3] = v.w;
        }
        __syncthreads();
        unsigned long long acc2[8][4];
#pragma unroll
        for (int i = 0; i < 8; i++)
#pragma unroll
            for (int jp = 0; jp < 4; jp++) acc2[i][jp] = 0ull;
#pragma unroll 8
        for (int kk = 0; kk < 32; kk++) {
            unsigned long long a2[8], b2[4];
#pragma unroll
            for (int i = 0; i < 8; i++) {
                float a = Qs[ty * 8 + i][kk];
                a2[i] = pk2(a, a);
            }
#pragma unroll
            for (int jp = 0; jp < 4; jp++)
                b2[jp] = pk2(Ks[32 * jp + tx][kk], Ks[32 * jp + 16 + tx][kk]);
#pragma unroll
            for (int i = 0; i < 8; i++)
#pragma unroll
                for (int jp = 0; jp < 4; jp++)
                    acc2[i][jp] = ffma2(a2[i], b2[jp], acc2[i][jp]);
        }
        int nv = nu - base;
#pragma unroll
        for (int jp = 0; jp < 4; jp++) {
            bool vlo = (32 * jp + tx) < nv;
            bool vhi = (32 * jp + 16 + tx) < nv;
#pragma unroll
            for (int i = 0; i < 8; i++) {
                float lo, hi; upk2(acc2[i][jp], lo, hi);
                if (vlo) mrow[i] = fmaxf(mrow[i], lo);
                if (vhi) mrow[i] = fmaxf(mrow[i], hi);
            }
        }
        __syncthreads();
    }
    // reduce row-max over the 16 tx lanes within each half-warp
#pragma unroll
    for (int off = 1; off < 16; off <<= 1)
#pragma unroll
        for (int i = 0; i < 8; i++)
            mrow[i] = fmaxf(mrow[i], __shfl_xor_sync(0xffffffffu, mrow[i], off));

    if (tx == 0) {
#pragma unroll
        for (int i = 0; i < 8; i++) {
            int qi = ty * 8 + i;
            float dot = 0.f;
#pragma unroll
            for (int d = 0; d < DH; d++) dot = fmaf(Qs[qi][d], ss[d], dot);
            g_M[bh * LL + q0 + qi] = mrow[i] - dot * (1.0f / (float)LL);
        }
    }
}

// ---------------- top-k: 40 smallest M, (value,index)-lexicographic ----------------
// shfl-based reduction (no smem tree / fewer barriers).
__global__ __launch_bounds__(256) void k_topk() {
    int bh = blockIdx.x;
    __shared__ unsigned long long keys[LL];
    __shared__ unsigned long long wred[8];
    int tid = threadIdx.x;
    int lane = tid & 31, w = tid >> 5;
    for (int l = tid; l < LL; l += 256) {
        unsigned int u = __float_as_uint(g_M[bh * LL + l]);
        u = (u & 0x80000000u) ? ~u : (u | 0x80000000u);   // monotone order map
        keys[l] = ((unsigned long long)u << 32) | (unsigned)l;
    }
    __syncthreads();
    for (int it = 0; it < UU; it++) {
        unsigned long long best = 0xFFFFFFFFFFFFFFFFull;
#pragma unroll
        for (int rep = 0; rep < LL / 256; rep++) {
            unsigned long long kk = keys[tid + rep * 256];
            if (kk < best) best = kk;
        }
#pragma unroll
        for (int off = 16; off > 0; off >>= 1) {
            unsigned long long o = __shfl_xor_sync(0xffffffffu, best, off);
            if (o < best) best = o;
        }
        if (lane == 0) wred[w] = best;
        __syncthreads();
        if (tid < 32) {
            unsigned long long b2 = (tid < 8) ? wred[tid] : 0xFFFFFFFFFFFFFFFFull;
#pragma unroll
            for (int off = 4; off > 0; off >>= 1) {
                unsigned long long o = __shfl_xor_sync(0xffffffffu, b2, off);
                if (o < b2) b2 = o;
            }
            if (tid == 0) {
                int idx = (int)(b2 & 0xFFFFFFFFull);
                g_top[bh * UU + it] = idx;
                keys[idx] = 0xFFFFFFFFFFFFFFFFull;
            }
        }
        __syncthreads();
    }
}

// ---------------- split-K flash attention over 40 selected queries ----------------
__global__ __launch_bounds__(256) void k_attn() {
    int bh = blockIdx.y, split = blockIdx.x;
    int b = bh >> 3, h = bh & 7;
    __shared__ __align__(16) float Qs[UU][DH];
    __shared__ float Ks[32][33];
    __shared__ float Vs[32][33];
    int tid = threadIdx.x;
    for (int e = tid; e < UU * 8; e += 256) {
        int r = e >> 3, c4 = (e & 7) << 2;
        int row = g_top[bh * UU + r];
        float4 v = *(const float4*)(g_qp + ((size_t)(bh * LL + row)) * DH + c4);
        *(float4*)&Qs[r][c4] = v;
    }
    int w = tid >> 5, lane = tid & 31;
    float m[5], lsum[5], acc[5];
#pragma unroll
    for (int qi = 0; qi < 5; qi++) { m[qi] = -1e30f; lsum[qi] = 0.f; acc[qi] = 0.f; }
    const float scale = 0.17677669529663687f;  // 1/sqrt(32)
    int k0 = split * (LL / NSPLIT);

    for (int sub = 0; sub < LL / NSPLIT; sub += 32) {
        __syncthreads();
        {
            int r = tid >> 3, c4 = (tid & 7) << 2;
            int key = k0 + sub + r;
            float4 kv = *(const float4*)(g_kp + ((size_t)(b * LL + key)) * DD + h * DH + c4);
            Ks[r][c4] = kv.x; Ks[r][c4 + 1] = kv.y; Ks[r][c4 + 2] = kv.z; Ks[r][c4 + 3] = kv.w;
            float4 vv = *(const float4*)(g_vp + ((size_t)(b * LL + key)) * DD + h * DH + c4);
            Vs[r][c4] = vv.x; Vs[r][c4 + 1] = vv.y; Vs[r][c4 + 2] = vv.z; Vs[r][c4 + 3] = vv.w;
        }
        __syncthreads();
#pragma unroll
        for (int qi = 0; qi < 5; qi++) {
            int q = w * 5 + qi;
            float s = 0.f;
#pragma unroll
            for (int d = 0; d < DH; d++) s = fmaf(Qs[q][d], Ks[lane][d], s);
            s *= scale;
            float smax = s;
#pragma unroll
            for (int off = 16; off > 0; off >>= 1)
                smax = fmaxf(smax, __shfl_xor_sync(0xffffffffu, smax, off));
            float mn = fmaxf(m[qi], smax);
            float corr = __expf(m[qi] - mn);
            float p = __expf(s - mn);
            float psum = p;
#pragma unroll
            for (int off = 16; off > 0; off >>= 1)
                psum += __shfl_xor_sync(0xffffffffu, psum, off);
            lsum[qi] = lsum[qi] * corr + psum;
            m[qi] = mn;
            float a = acc[qi] * corr;
#pragma unroll
            for (int j = 0; j < 32; j++) {
                float pj = __shfl_sync(0xffffffffu, p, j);
                a = fmaf(pj, Vs[j][lane], a);
            }
            acc[qi] = a;
        }
    }
#pragma unroll
    for (int qi = 0; qi < 5; qi++) {
        int q = w * 5 + qi;
        int pidx = (bh * NSPLIT + split) * UU + q;
        if (lane == 0) { g_pm[pidx] = m[qi]; g_pl[pidx] = lsum[qi]; }
        g_pacc[(size_t)pidx * DH + lane] = acc[qi];
    }
}

// ---------------- combine split-softmax partials ----------------
__global__ void k_comb() {
    int q = blockIdx.x, bh = blockIdx.y, lane = threadIdx.x;  // 32 threads
    float mstar = -1e30f;
#pragma unroll
    for (int s = 0; s < NSPLIT; s++)
        mstar = fmaxf(mstar, g_pm[(bh * NSPLIT + s) * UU + q]);
    float lt = 0.f, o = 0.f;
#pragma unroll
    for (int s = 0; s < NSPLIT; s++) {
        int pidx = (bh * NSPLIT + s) * UU + q;
        float wgt = __expf(g_pm[pidx] - mstar);
        lt += wgt * g_pl[pidx];
        o += wgt * g_pacc[(size_t)pidx * DH + lane];
    }
    g_attn[(bh * UU + q) * DH + lane] = o / lt;
}

// ---------------- final projection: out = mid @ Wc^T + bc ----------------
__global__ __launch_bounds__(256) void k_final(const float* __restrict__ Wc,
                                               const float* __restrict__ bc,
                                               float* __restrict__ out)
{
    int c0 = blockIdx.x * 32;
    int r0 = blockIdx.y * 8;
    __shared__ float Wt[DD][33];
    int tid = threadIdx.x;
    for (int e = tid; e < 2048; e += 256) {
        int cl = e >> 6, d4 = (e & 63) << 2;
        float4 v = *(const float4*)(Wc + (size_t)(c0 + cl) * DD + d4);
        Wt[d4][cl] = v.x; Wt[d4 + 1][cl] = v.y; Wt[d4 + 2][cl] = v.z; Wt[d4 + 3][cl] = v.w;
    }
    __syncthreads();
    int cl = tid & 31, rb = tid >> 5;
    int r = r0 + rb;                 // 0..159 = b*40 + j
    int b = r / UU, j = r % UU;
    float acc = bc[c0 + cl];
#pragma unroll 8
    for (int d = 0; d < DD; d++) {
        float x = g_attn[(((b * HH + (d >> 5)) * UU + j) * DH) + (d & 31)];
        acc = fmaf(x, Wt[d][cl], acc);
    }
    out[(size_t)r * DD + c0 + cl] = acc;
}

// ---------------- launcher ----------------
extern "C" void kernel_launch(void* const* d_in, const int* in_sizes, int n_in,
                              void* d_out, int out_size)
{
    const float* q   = (const float*)d_in[0];
    const float* k   = (const float*)d_in[1];
    const float* v   = (const float*)d_in[2];
    const float* Wq  = (const float*)d_in[3];
    const float* bq  = (const float*)d_in[4];
    const float* Wk  = (const float*)d_in[5];
    const float* bk  = (const float*)d_in[6];
    const float* Wv  = (const float*)d_in[7];
    const float* bv  = (const float*)d_in[8];
    const float* Wc  = (const float*)d_in[9];
    const float* bc  = (const float*)d_in[10];
    const int*   idx = (const int*)d_in[11];
    float* out = (float*)d_out;

    k_init<<<8, 256>>>();
    k_uniq<<<8, 256>>>(idx);
    k_proj<<<dim3(2, 64, 3), 256>>>(q, k, v, Wq, Wk, Wv, bq, bk, bv);
    k_ssum<<<dim3(BHH, SCH), 256>>>();
    k_m<<<dim3(16, 32), 256>>>();
    k_topk<<<32, 256>>>();
    k_attn<<<dim3(NSPLIT, 32), 256>>>();
    k_comb<<<dim3(UU, 32), 32>>>();
    k_final<<<dim3(8, 20), 256>>>(Wc, bc, out);
}